// round 1
// baseline (speedup 1.0000x reference)
#include <cuda_runtime.h>
#include <cstring>

// Problem constants
#define NBINS   64
#define SPTS    1024      // points per graph
#define NGRAPH  64
#define TILE    128
#define NTILE   8         // SPTS / TILE
#define NPAIRS  36        // NTILE*(NTILE+1)/2 tile pairs
#define HIDDEN  256

// Global per-graph histograms (integer-exact, deterministic)
__device__ int g_hist[NGRAPH * NBINS];

// ---------- f32x2 packed helpers (Blackwell sm_10x) ----------
__device__ __forceinline__ unsigned long long f2_pack(float a, float b) {
    unsigned long long r;
    asm("mov.b64 %0, {%1, %2};" : "=l"(r) : "f"(a), "f"(b));
    return r;
}
__device__ __forceinline__ void f2_unpack(unsigned long long v, float& a, float& b) {
    asm("mov.b64 {%0, %1}, %2;" : "=f"(a), "=f"(b) : "l"(v));
}
__device__ __forceinline__ unsigned long long f2_add(unsigned long long a, unsigned long long b) {
    unsigned long long r;
    asm("add.rn.f32x2 %0, %1, %2;" : "=l"(r) : "l"(a), "l"(b));
    return r;
}
__device__ __forceinline__ unsigned long long f2_mul(unsigned long long a, unsigned long long b) {
    unsigned long long r;
    asm("mul.rn.f32x2 %0, %1, %2;" : "=l"(r) : "l"(a), "l"(b));
    return r;
}
__device__ __forceinline__ unsigned long long f2_fma(unsigned long long a, unsigned long long b,
                                                     unsigned long long c) {
    unsigned long long r;
    asm("fma.rn.f32x2 %0, %1, %2, %3;" : "=l"(r) : "l"(a), "l"(b), "l"(c));
    return r;
}
__device__ __forceinline__ float fsqrt_approx(float x) {
    float y;
    asm("sqrt.approx.f32 %0, %1;" : "=f"(y) : "f"(x));
    return y;
}

// ---------- kernel 0: zero global histograms ----------
__global__ void zero_hist_kernel() {
    int i = blockIdx.x * blockDim.x + threadIdx.x;
    if (i < NGRAPH * NBINS) g_hist[i] = 0;
}

// ---------- kernel 1: pairwise-distance histogram ----------
// grid = (36 tile-pairs, 64 graphs), block = 128 threads.
// Thread t owns row i = t of the row tile and iterates all 128 columns of the
// col tile (2 at a time via f32x2). Counts go into a per-THREAD private shared
// histogram hist[bin][tid] (bank-conflict-free RMW, no atomics).
__global__ __launch_bounds__(TILE) void hist_kernel(const float* __restrict__ pos) {
    __shared__ unsigned int sh_hist[NBINS * TILE];        // 32 KB, [bin][tid]
    __shared__ __align__(16) float xs[TILE], ys[TILE], zs[TILE];
    __shared__ unsigned int sh_part[TILE];

    const int tid = threadIdx.x;
    const int g   = blockIdx.y;

    // map blockIdx.x -> (ti, tj), ti <= tj
    int ti = 0, rem = blockIdx.x;
    while (rem >= NTILE - ti) { rem -= NTILE - ti; ++ti; }
    const int tj = ti + rem;

    // zero private histograms
#pragma unroll
    for (int r = 0; r < NBINS; ++r) sh_hist[r * TILE + tid] = 0;

    const float SCALE = (float)NBINS / 25.0f;   // 2.56f

    // load column tile (SoA, pre-scaled)
    {
        const float* q = pos + ((size_t)(g * SPTS + tj * TILE + tid)) * 3;
        xs[tid] = q[0] * SCALE;
        ys[tid] = q[1] * SCALE;
        zs[tid] = q[2] * SCALE;
    }
    // row point (pre-scaled, negated, packed for f32x2 adds)
    const float* r = pos + ((size_t)(g * SPTS + ti * TILE + tid)) * 3;
    const float xi = r[0] * SCALE, yi = r[1] * SCALE, zi = r[2] * SCALE;
    const unsigned long long nxi = f2_pack(-xi, -xi);
    const unsigned long long nyi = f2_pack(-yi, -yi);
    const unsigned long long nzi = f2_pack(-zi, -zi);

    __syncthreads();

    const unsigned long long* xs2 = (const unsigned long long*)xs;
    const unsigned long long* ys2 = (const unsigned long long*)ys;
    const unsigned long long* zs2 = (const unsigned long long*)zs;

    unsigned int* myhist = sh_hist + tid;            // stride TILE per bin
    const int lim = (ti == tj) ? tid : -1;           // diagonal: need j > i

    const float MAGIC = 8388607.5f;                  // 2^23 - 0.5 -> floor()

#pragma unroll 4
    for (int h = 0; h < TILE / 2; ++h) {
        const int j0 = 2 * h;
        unsigned long long dx = f2_add(xs2[h], nxi);
        unsigned long long dy = f2_add(ys2[h], nyi);
        unsigned long long dz = f2_add(zs2[h], nzi);
        unsigned long long d2 = f2_fma(dx, dx, f2_fma(dy, dy, f2_mul(dz, dz)));
        float d2a, d2b;
        f2_unpack(d2, d2a, d2b);

        // pair (i, j0)
        {
            unsigned int k = __float_as_uint(fsqrt_approx(d2a) + MAGIC) & 1023u;
            unsigned int inc = (k < 64u && j0 > lim) ? 1u : 0u;
            unsigned int b = min(k, 63u);
            myhist[b * TILE] += inc;                 // LDS + IADD + STS
        }
        // pair (i, j0+1)
        {
            unsigned int k = __float_as_uint(fsqrt_approx(d2b) + MAGIC) & 1023u;
            unsigned int inc = (k < 64u && (j0 + 1) > lim) ? 1u : 0u;
            unsigned int b = min(k, 63u);
            myhist[b * TILE] += inc;
        }
    }

    __syncthreads();

    // reduce 128 private hists -> 64 bins (staggered to stay conflict-free)
    {
        const int bin = tid & 63;
        const int seg = tid >> 6;                    // 0 or 1
        unsigned int s = 0;
#pragma unroll 8
        for (int k = 0; k < 64; ++k) {
            int col = seg * 64 + ((k + bin) & 63);
            s += sh_hist[bin * TILE + col];
        }
        sh_part[tid] = s;
    }
    __syncthreads();
    if (tid < NBINS) {
        unsigned int tot = sh_part[tid] + sh_part[tid + 64];
        if (tot) atomicAdd(&g_hist[g * NBINS + tid], (int)tot);
    }
}

// ---------- kernel 2: normalize + MLP ----------
// grid = 64 graphs, block = 256 threads (one per hidden unit / output unit)
__global__ __launch_bounds__(HIDDEN) void mlp_kernel(const float* __restrict__ W1,
                                                     const float* __restrict__ b1,
                                                     const float* __restrict__ W2,
                                                     const float* __restrict__ b2,
                                                     float* __restrict__ out) {
    const int g = blockIdx.x;
    const int t = threadIdx.x;
    __shared__ float hn[NBINS];
    __shared__ float h[HIDDEN];
    __shared__ float inv;

    if (t < NBINS) hn[t] = (float)g_hist[g * NBINS + t];
    __syncthreads();
    if (t == 0) {
        float s = 0.0f;
        for (int k = 0; k < NBINS; ++k) s += hn[k];
        inv = __fdividef(1.0f, s + 1e-8f);
    }
    __syncthreads();

    // layer 1: x = inv * dot(cnt, W1[t,:]) + b1[t], silu
    float dot = 0.0f;
    const float4* w1r = reinterpret_cast<const float4*>(W1 + t * NBINS);
#pragma unroll
    for (int k = 0; k < NBINS / 4; ++k) {
        float4 w = w1r[k];
        dot += w.x * hn[4 * k] + w.y * hn[4 * k + 1] + w.z * hn[4 * k + 2] + w.w * hn[4 * k + 3];
    }
    float x = fmaf(dot, inv, b1[t]);
    float sig = 1.0f / (1.0f + __expf(-x));
    h[t] = x * sig;
    __syncthreads();

    // layer 2
    float acc = b2[t];
    const float4* w2r = reinterpret_cast<const float4*>(W2 + t * HIDDEN);
#pragma unroll 8
    for (int k = 0; k < HIDDEN / 4; ++k) {
        float4 w = w2r[k];
        acc += w.x * h[4 * k] + w.y * h[4 * k + 1] + w.z * h[4 * k + 2] + w.w * h[4 * k + 3];
    }
    out[g * HIDDEN + t] = acc;
}

extern "C" void kernel_launch(void* const* d_in, const int* in_sizes, int n_in,
                              void* d_out, int out_size) {
    // Size-based input identification (robust to dict vs alphabetical order):
    // pos: 196608 f32, W1: 16384 f32, b1/b2: 256 f32 (in order), W2: first 65536,
    // batch: 65536 i32 (unused; setup guarantees contiguous equal segments).
    int iPos = 0, iW1 = 1, iW2 = 3, ib1 = 2, ib2 = 4;
    {
        int found_pos = -1, found_w1 = -1, found_w2 = -1, found_b1 = -1, found_b2 = -1;
        for (int i = 0; i < n_in; ++i) {
            int s = in_sizes[i];
            if (s == 196608 && found_pos < 0) found_pos = i;
            else if (s == 16384 && found_w1 < 0) found_w1 = i;
            else if (s == 65536 && found_w2 < 0) found_w2 = i;
            else if (s == 256) { if (found_b1 < 0) found_b1 = i; else if (found_b2 < 0) found_b2 = i; }
        }
        if (found_pos >= 0 && found_w1 >= 0 && found_w2 >= 0 && found_b1 >= 0 && found_b2 >= 0) {
            iPos = found_pos; iW1 = found_w1; iW2 = found_w2; ib1 = found_b1; ib2 = found_b2;
        }
    }

    const float* pos = (const float*)d_in[iPos];
    const float* W1  = (const float*)d_in[iW1];
    const float* b1  = (const float*)d_in[ib1];
    const float* W2  = (const float*)d_in[iW2];
    const float* b2  = (const float*)d_in[ib2];
    float* out = (float*)d_out;

    zero_hist_kernel<<<16, 256>>>();
    hist_kernel<<<dim3(NPAIRS, NGRAPH), TILE>>>(pos);
    mlp_kernel<<<NGRAPH, HIDDEN>>>(W1, b1, W2, b2, out);
}